// round 9
// baseline (speedup 1.0000x reference)
#include <cuda_runtime.h>
#include <cuda_fp16.h>
#include <cstdint>

#define HIDDEN 1024
#define HEADS  16
#define HD     64
#define KP     256
#define BSZ    4
#define QLEN   4096
#define MR     (BSZ*QLEN)   // 16384

// ---------------- scratch (device globals) ----------------------------------
__device__ __half g_hs_h [MR*HIDDEN];
__device__ __half g_hs_th[(size_t)BSZ*HIDDEN*QLEN];
__device__ __half g_q_h  [MR*HIDDEN];
__device__ __half g_o_h  [MR*HIDDEN];
__device__ __half g_kp_h [BSZ*KP*HIDDEN];
__device__ __half g_vp_h [BSZ*KP*HIDDEN];
__device__ __half g_vpT_h[BSZ*KP*HIDDEN];
__device__ __half g_hE_h [BSZ*KP*HIDDEN];
__device__ __half g_hF_h [BSZ*KP*HIDDEN];
__device__ __half g_Et_h [KP*QLEN];
__device__ __half g_Ft_h [KP*QLEN];
__device__ __half g_Wq_h [HIDDEN*HIDDEN];
__device__ __half g_Wk_h [HIDDEN*HIDDEN];
__device__ __half g_Wv_h [HIDDEN*HIDDEN];
__device__ float  g_part [16 * KP * HIDDEN];
__device__ __half g_Wo_h [HIDDEN*HIDDEN];

// ============================== helpers =====================================
#define CP_ASYNC16(s, g) \
    asm volatile("cp.async.cg.shared.global [%0], [%1], 16;" :: "r"(s), "l"(g))
#define CP_ASYNC_COMMIT() asm volatile("cp.async.commit_group;")
#define CP_ASYNC_WAIT1()  asm volatile("cp.async.wait_group 1;" ::: "memory")
#define CP_ASYNC_WAIT0()  asm volatile("cp.async.wait_group 0;" ::: "memory")

__device__ __forceinline__ uint32_t smem_u32(const void* p) {
    uint32_t a;
    asm("{ .reg .u64 t; cvta.to.shared.u64 t, %1; cvt.u32.u64 %0, t; }"
        : "=r"(a) : "l"(p));
    return a;
}

#define MMA_F16(c, a0, a1, a2, a3, b0, b1)                                    \
    asm volatile("mma.sync.aligned.m16n8k16.row.col.f32.f16.f16.f32 "         \
        "{%0,%1,%2,%3}, {%4,%5,%6,%7}, {%8,%9}, {%0,%1,%2,%3};"               \
        : "+f"((c)[0]), "+f"((c)[1]), "+f"((c)[2]), "+f"((c)[3])              \
        : "r"(a0), "r"(a1), "r"(a2), "r"(a3), "r"(b0), "r"(b1))

#define LDSM4(d0, d1, d2, d3, a)                                              \
    asm volatile("ldmatrix.sync.aligned.m8n8.x4.shared.b16 {%0,%1,%2,%3}, [%4];" \
        : "=r"(d0), "=r"(d1), "=r"(d2), "=r"(d3) : "r"(a))

__device__ __forceinline__ uint32_t pack_h2(float lo, float hi) {
    __half2 h = __floats2half2_rn(lo, hi);
    return *(uint32_t*)&h;
}

// ---- GEMM tiling: BM=128, BN=64, BK=64 halves, 2-stage, 3 CTAs/SM -----------
#define ASTH 72                        // smem row stride (halves); 144B rows
#define ABYT (128*ASTH*2)              // 18432 B (A tile)
#define BBYT (64*ASTH*2)               // 9216 B  (B tile)
#define STG  (ABYT + BBYT)             // 27648 B per stage
#define SMEM_G (2*STG)                 // 55296 B

struct G { const __half* A; const __half* B; __half* Ch; float* Cf; };

__device__ __forceinline__ void stage_a(const __half* P, int ldk,
                                        uint32_t sdst, int r0, int k0, int tid)
{
    #pragma unroll
    for (int i = 0; i < 4; i++) {
        int c = tid + i * 256;          // 0..1023 : 128 rows x 8 chunks
        int row = c >> 3, kc = c & 7;
        CP_ASYNC16(sdst + row * 144 + kc * 16,
                   P + (size_t)(r0 + row) * ldk + k0 + kc * 8);
    }
}
__device__ __forceinline__ void stage_b(const __half* P, int ldk,
                                        uint32_t sdst, int r0, int k0, int tid)
{
    #pragma unroll
    for (int i = 0; i < 2; i++) {
        int c = tid + i * 256;          // 0..511 : 64 rows x 8 chunks
        int row = c >> 3, kc = c & 7;
        CP_ASYNC16(sdst + row * 144 + kc * 16,
                   P + (size_t)(r0 + row) * ldk + k0 + kc * 8);
    }
}

// warp tile 32(m) x 32(n); per BK=64 slab: 16 ldsm4, 32 mma
#define GEMM_SLAB64(bA, bB, aoff, boff, cacc)                                 \
    _Pragma("unroll")                                                         \
    for (int ks2 = 0; ks2 < 4; ks2++) {                                       \
        uint32_t ra0[4], ra1[4], rb0[4], rb1[4];                              \
        LDSM4(ra0[0], ra0[1], ra0[2], ra0[3], (bA) + (aoff) + ks2*32);        \
        LDSM4(ra1[0], ra1[1], ra1[2], ra1[3],                                 \
              (bA) + (aoff) + 16*ASTH*2 + ks2*32);                            \
        LDSM4(rb0[0], rb0[1], rb0[2], rb0[3], (bB) + (boff) + ks2*32);        \
        LDSM4(rb1[0], rb1[1], rb1[2], rb1[3],                                 \
              (bB) + (boff) + 16*ASTH*2 + ks2*32);                            \
        MMA_F16(cacc[0][0], ra0[0],ra0[1],ra0[2],ra0[3], rb0[0],rb0[2]);      \
        MMA_F16(cacc[0][1], ra0[0],ra0[1],ra0[2],ra0[3], rb0[1],rb0[3]);      \
        MMA_F16(cacc[0][2], ra0[0],ra0[1],ra0[2],ra0[3], rb1[0],rb1[2]);      \
        MMA_F16(cacc[0][3], ra0[0],ra0[1],ra0[2],ra0[3], rb1[1],rb1[3]);      \
        MMA_F16(cacc[1][0], ra1[0],ra1[1],ra1[2],ra1[3], rb0[0],rb0[2]);      \
        MMA_F16(cacc[1][1], ra1[0],ra1[1],ra1[2],ra1[3], rb0[1],rb0[3]);      \
        MMA_F16(cacc[1][2], ra1[0],ra1[1],ra1[2],ra1[3], rb1[0],rb1[2]);      \
        MMA_F16(cacc[1][3], ra1[0],ra1[1],ra1[2],ra1[3], rb1[1],rb1[3]);      \
    }

// ============================================================================
// NT GEMM fp16: C[M,N] = A[M,K] @ B[N,K]^T.  Block tile 128x64, 8 warps.
// ============================================================================
__global__ __launch_bounds__(256, 3) void gemm_nt_h(
    G g0, G g1, G g2, int N, int K, int ylim12)
{
    extern __shared__ char smem[];
    const int z = blockIdx.z;
    if (z > 0 && (int)blockIdx.y >= ylim12) return;
    const G g = (z == 0) ? g0 : (z == 1 ? g1 : g2);

    const int tid = threadIdx.x, lane = tid & 31, wid = tid >> 5;
    const int m0 = blockIdx.y * 128, n0 = blockIdx.x * 64;
    const int wm = (wid & 3) * 32, wn = (wid >> 2) * 32;
    const int gq = lane >> 2, r = lane & 3;
    const int lrow = lane & 15, lhi = (lane >> 4) * 8;
    const uint32_t sb = smem_u32(smem);
    const uint32_t aoff = ((wm + lrow) * ASTH + lhi) * 2;
    const uint32_t boff = ABYT + ((wn + lrow) * ASTH + lhi) * 2;

    float cacc[2][4][4];
    #pragma unroll
    for (int i = 0; i < 2; i++)
        #pragma unroll
        for (int j = 0; j < 4; j++)
            #pragma unroll
            for (int q = 0; q < 4; q++) cacc[i][j][q] = 0.0f;

    const int T = K / 64;
    stage_a(g.A, K, sb,        m0, 0, tid);
    stage_b(g.B, K, sb + ABYT, n0, 0, tid);
    CP_ASYNC_COMMIT();

    for (int t = 0; t < T; t++) {
        CP_ASYNC_WAIT0();
        __syncthreads();
        if (t + 1 < T) {
            uint32_t base = sb + ((t + 1) & 1) * STG;
            stage_a(g.A, K, base,        m0, (t + 1) * 64, tid);
            stage_b(g.B, K, base + ABYT, n0, (t + 1) * 64, tid);
            CP_ASYNC_COMMIT();
        }
        uint32_t bA = sb + (t & 1) * STG;
        GEMM_SLAB64(bA, bA, aoff, boff, cacc);
    }

    #pragma unroll
    for (int i = 0; i < 2; i++) {
        int row = m0 + wm + i * 16 + gq;
        #pragma unroll
        for (int j = 0; j < 4; j++) {
            int col = n0 + wn + j * 8 + r * 2;
            if (g.Cf) {
                *(float2*)(g.Cf + (size_t)row * N + col) =
                    make_float2(cacc[i][j][0], cacc[i][j][1]);
                *(float2*)(g.Cf + (size_t)(row + 8) * N + col) =
                    make_float2(cacc[i][j][2], cacc[i][j][3]);
            } else {
                *(__half2*)(g.Ch + (size_t)row * N + col) =
                    __floats2half2_rn(cacc[i][j][0], cacc[i][j][1]);
                *(__half2*)(g.Ch + (size_t)(row + 8) * N + col) =
                    __floats2half2_rn(cacc[i][j][2], cacc[i][j][3]);
            }
        }
    }
}

// ============================================================================
// Split-K GEMM for hE/hF (block tile 128x64, 3 CTAs/SM).
// grid (16, 2, 16): bz -> isF = bz&1, b = (bz>>1)&3, ks = bz>>3.
// ============================================================================
__global__ __launch_bounds__(256, 3) void gemm_nt_sk()
{
    extern __shared__ char smem[];
    const int bz = blockIdx.z;
    const int isF = bz & 1, b = (bz >> 1) & 3, ks = bz >> 3;
    const __half* A = isF ? g_Ft_h : g_Et_h;
    const __half* B = g_hs_th + (size_t)b * HIDDEN * QLEN;
    float* Cp = g_part + (size_t)(ks * 8 + (bz & 7)) * KP * HIDDEN;

    const int tid = threadIdx.x, lane = tid & 31, wid = tid >> 5;
    const int m0 = blockIdx.y * 128, n0 = blockIdx.x * 64;
    const int wm = (wid & 3) * 32, wn = (wid >> 2) * 32;
    const int gq = lane >> 2, r = lane & 3;
    const int lrow = lane & 15, lhi = (lane >> 4) * 8;
    const uint32_t sb = smem_u32(smem);
    const uint32_t aoff = ((wm + lrow) * ASTH + lhi) * 2;
    const uint32_t boff = ABYT + ((wn + lrow) * ASTH + lhi) * 2;
    const int kbase = ks * 2048, T = 32;

    float cacc[2][4][4];
    #pragma unroll
    for (int i = 0; i < 2; i++)
        #pragma unroll
        for (int j = 0; j < 4; j++)
            #pragma unroll
            for (int q = 0; q < 4; q++) cacc[i][j][q] = 0.0f;

    stage_a(A, QLEN, sb,        m0, kbase, tid);
    stage_b(B, QLEN, sb + ABYT, n0, kbase, tid);
    CP_ASYNC_COMMIT();

    for (int t = 0; t < T; t++) {
        CP_ASYNC_WAIT0();
        __syncthreads();
        if (t + 1 < T) {
            uint32_t base = sb + ((t + 1) & 1) * STG;
            stage_a(A, QLEN, base,        m0, kbase + (t + 1) * 64, tid);
            stage_b(B, QLEN, base + ABYT, n0, kbase + (t + 1) * 64, tid);
            CP_ASYNC_COMMIT();
        }
        uint32_t bA = sb + (t & 1) * STG;
        GEMM_SLAB64(bA, bA, aoff, boff, cacc);
    }

    #pragma unroll
    for (int i = 0; i < 2; i++) {
        int row = m0 + wm + i * 16 + gq;
        #pragma unroll
        for (int j = 0; j < 4; j++) {
            int col = n0 + wn + j * 8 + r * 2;
            *(float2*)(Cp + (size_t)row * HIDDEN + col) =
                make_float2(cacc[i][j][0], cacc[i][j][1]);
            *(float2*)(Cp + (size_t)(row + 8) * HIDDEN + col) =
                make_float2(cacc[i][j][2], cacc[i][j][3]);
        }
    }
}

__global__ void reduce_hEF()
{
    int idx = blockIdx.x * 256 + threadIdx.x;
    int p = idx >> 16;
    int w4 = idx & 65535;
    const float4 x = ((const float4*)(g_part + (size_t)p       * KP*HIDDEN))[w4];
    const float4 y = ((const float4*)(g_part + (size_t)(8 + p) * KP*HIDDEN))[w4];
    int isF = p & 1, b = p >> 1;
    __half* dst = (isF ? g_hF_h : g_hE_h) + (size_t)b * KP * HIDDEN + w4 * 4;
    ((__half2*)dst)[0] = __floats2half2_rn(x.x + y.x, x.y + y.y);
    ((__half2*)dst)[1] = __floats2half2_rn(x.z + y.z, x.w + y.w);
}

// ============================================================================
// fp16 mma attention: register P, split cp.async groups (unchanged — proven).
// ============================================================================
#define QST 72
#define KST 72
#define VST 264
#define QSO 0
#define KSO (128*QST)
#define VSO (KSO + 256*KST)
#define ATTN_SMEM ((VSO + 64*VST) * 2)  // 89088 B

__global__ __launch_bounds__(256, 2) void attn_h()
{
    extern __shared__ __half smh[];

    const int tid  = threadIdx.x;
    const int lane = tid & 31;
    const int wid  = tid >> 5;
    const int gq   = lane >> 2, r = lane & 3;
    const int lrow = lane & 15, lhi = (lane >> 4) * 8;
    const int q0   = blockIdx.x << 7;
    const int h    = blockIdx.y;
    const int b    = blockIdx.z;

    const __half* qb  = g_q_h  + ((size_t)b*QLEN + q0) * HIDDEN + h*HD;
    const __half* kpb = g_kp_h + (size_t)b*KP*HIDDEN + h*HD;
    const __half* vtb = g_vpT_h + ((size_t)b*HEADS + h) * HD * KP;
    const uint32_t sb = smem_u32(smh);

    #pragma unroll
    for (int i = 0; i < 4; i++) {
        int c = tid + i * 256;
        int row = c >> 3, kc = c & 7;
        CP_ASYNC16(sb + (QSO + row * QST) * 2 + kc * 16,
                   qb + (size_t)row * HIDDEN + kc * 8);
    }
    #pragma unroll
    for (int i = 0; i < 8; i++) {
        int c = tid + i * 256;
        int row = c >> 3, kc = c & 7;
        CP_ASYNC16(sb + (KSO + row * KST) * 2 + kc * 16,
                   kpb + (size_t)row * HIDDEN + kc * 8);
    }
    CP_ASYNC_COMMIT();
    #pragma unroll
    for (int i = 0; i < 8; i++) {
        int c = tid + i * 256;
        int row = c >> 5, kc = c & 31;
        CP_ASYNC16(sb + (VSO + row * VST) * 2 + kc * 16,
                   vtb + (size_t)row * KP + kc * 8);
    }
    CP_ASYNC_COMMIT();

    CP_ASYNC_WAIT1();
    __syncthreads();

    const int wm = wid * 16;
    const uint32_t qaoff = sb + ((QSO + (wm + lrow) * QST + lhi) * 2);
    uint32_t QA[4][4];
    #pragma unroll
    for (int ks = 0; ks < 4; ks++)
        LDSM4(QA[ks][0], QA[ks][1], QA[ks][2], QA[ks][3], qaoff + ks * 32);

    const uint32_t kboff = sb + ((KSO + lrow * KST + lhi) * 2);
    uint32_t P[64];
    float sum0 = 0.0f, sum1 = 0.0f;

    #pragma unroll
    for (int jp = 0; jp < 16; jp++) {
        float c0[4] = {0.f, 0.f, 0.f, 0.f};
        float c1[4] = {0.f, 0.f, 0.f, 0.f};
        #pragma unroll
        for (int ks = 0; ks < 4; ks++) {
            uint32_t rb[4];
            LDSM4(rb[0], rb[1], rb[2], rb[3],
                  kboff + jp * (16*KST*2) + ks * 32);
            MMA_F16(c0, QA[ks][0], QA[ks][1], QA[ks][2], QA[ks][3], rb[0], rb[2]);
            MMA_F16(c1, QA[ks][0], QA[ks][1], QA[ks][2], QA[ks][3], rb[1], rb[3]);
        }
        float e00 = __expf(c0[0] * 0.125f), e01 = __expf(c0[1] * 0.125f);
        float e02 = __expf(c0[2] * 0.125f), e03 = __expf(c0[3] * 0.125f);
        float e10 = __expf(c1[0] * 0.125f), e11 = __expf(c1[1] * 0.125f);
        float e12 = __expf(c1[2] * 0.125f), e13 = __expf(c1[3] * 0.125f);
        sum0 += (e00 + e01) + (e10 + e11);
        sum1 += (e02 + e03) + (e12 + e13);
        P[4*jp + 0] = pack_h2(e00, e01);
        P[4*jp + 1] = pack_h2(e02, e03);
        P[4*jp + 2] = pack_h2(e10, e11);
        P[4*jp + 3] = pack_h2(e12, e13);
    }

    sum0 += __shfl_xor_sync(0xffffffffu, sum0, 1);
    sum0 += __shfl_xor_sync(0xffffffffu, sum0, 2);
    sum1 += __shfl_xor_sync(0xffffffffu, sum1, 1);
    sum1 += __shfl_xor_sync(0xffffffffu, sum1, 2);
    const float ri0 = 1.0f / sum0, ri1 = 1.0f / sum1;

    CP_ASYNC_WAIT0();
    __syncthreads();

    const uint32_t vboff = sb + ((VSO + lrow * VST + lhi) * 2);
    float c2[8][4];
    #pragma unroll
    for (int j = 0; j < 8; j++)
        #pragma unroll
        for (int q = 0; q < 4; q++) c2[j][q] = 0.0f;

    #pragma unroll
    for (int t = 0; t < 16; t++) {
        #pragma unroll
        for (int g = 0; g < 4; g++) {
            uint32_t rb[4];
            LDSM4(rb[0], rb[1], rb[2], rb[3],
                  vboff + g * (16*VST*2) + t * 32);
            MMA_F16(c2[2*g],   P[4*t+0], P[4*t+1], P[4*t+2], P[4*t+3], rb[0], rb[2]);
            MMA_F16(c2[2*g+1], P[4*t+0], P[4*t+1], P[4*t+2], P[4*t+3], rb[1], rb[3]);
        }
    }

    __half* ob = g_o_h + ((size_t)b*QLEN + q0 + wm) * HIDDEN + h*HD;
    #pragma unroll
    for (int j = 0; j < 8; j++) {
        int col = j * 8 + r * 2;
        *(__half2*)(ob + (size_t)gq * HIDDEN + col) =
            __floats2half2_rn(c2[j][0] * ri0, c2[j][1] * ri0);
        *(__half2*)(ob + (size_t)(gq + 8) * HIDDEN + col) =
            __floats2half2_rn(c2[j][2] * ri1, c2[j][3] * ri1);
    }
}

// ============================================================================
// Conversion / transpose pre-passes (unchanged)
// ============================================================================
__global__ void conv_hs(const float* __restrict__ hs)
{
    __shared__ float t[64][33];
    int b = blockIdx.z;
    int s0 = blockIdx.x * 64, n0 = blockIdx.y * 32;
    int tx = threadIdx.x, ty = threadIdx.y;
    #pragma unroll
    for (int i = 0; i < 8; i++) {
        int s = s0 + ty + i * 8;
        float v = hs[((size_t)b * QLEN + s) * HIDDEN + n0 + tx];
        t[ty + i * 8][tx] = v;
        g_hs_h[((size_t)b * QLEN + s) * HIDDEN + n0 + tx] = __float2half_rn(v);
    }
    __syncthreads();
    #pragma unroll
    for (int i = 0; i < 4; i++) {
        int n = n0 + ty + i * 8;
        __half2 hv = __floats2half2_rn(t[2*tx][ty + i * 8], t[2*tx + 1][ty + i * 8]);
        *(__half2*)&g_hs_th[((size_t)b * HIDDEN + n) * QLEN + s0 + 2*tx] = hv;
    }
}

__global__ void conv_w4(const float* w0, const float* w1,
                        const float* w2, const float* w3)
{
    const float* src = (blockIdx.y == 0) ? w0 : (blockIdx.y == 1) ? w1
                     : (blockIdx.y == 2) ? w2 : w3;
    __half* dst = (blockIdx.y == 0) ? g_Wq_h : (blockIdx.y == 1) ? g_Wk_h
                : (blockIdx.y == 2) ? g_Wv_h : g_Wo_h;
    int i = blockIdx.x * 256 + threadIdx.x;
    float4 v = ((const float4*)src)[i];
    ((__half2*)dst)[i*2]   = __floats2half2_rn(v.x, v.y);
    ((__half2*)dst)[i*2+1] = __floats2half2_rn(v.z, v.w);
}

__global__ void transpose_efh(const float* __restrict__ E, const float* __restrict__ F)
{
    __shared__ float t[64][33];
    const float* src = blockIdx.z ? F : E;
    __half* dst = blockIdx.z ? g_Ft_h : g_Et_h;
    int s0 = blockIdx.x * 64, m0 = blockIdx.y * 32;
    int tx = threadIdx.x, ty = threadIdx.y;
    #pragma unroll
    for (int i = 0; i < 8; i++)
        t[ty + i * 8][tx] = src[(size_t)(s0 + ty + i * 8) * KP + m0 + tx];
    __syncthreads();
    #pragma unroll
    for (int i = 0; i < 4; i++) {
        int m = m0 + ty + i * 8;
        __half2 hv = __floats2half2_rn(t[2*tx][ty + i * 8], t[2*tx + 1][ty + i * 8]);
        *(__half2*)&dst[(size_t)m * QLEN + s0 + 2*tx] = hv;
    }
}

__global__ void transpose_vp()
{
    __shared__ __half t[32][33];
    int b = blockIdx.z;
    int k0 = blockIdx.x * 32, n0 = blockIdx.y * 32;
    int tx = threadIdx.x, ty = threadIdx.y;
    #pragma unroll
    for (int i = 0; i < 4; i++)
        t[ty + i * 8][tx] =
            g_vp_h[((size_t)b * KP + k0 + ty + i * 8) * HIDDEN + n0 + tx];
    __syncthreads();
    #pragma unroll
    for (int i = 0; i < 4; i++)
        g_vpT_h[((size_t)b * HIDDEN + n0 + ty + i * 8) * KP + k0 + tx] =
            t[tx][ty + i * 8];
}

// ---------------------------------------------------------------------------
extern "C" void kernel_launch(void* const* d_in, const int* in_sizes, int n_in,
                              void* d_out, int out_size)
{
    const float* hs = (const float*)d_in[0];
    const float* Wq = (const float*)d_in[1];
    const float* Wk = (const float*)d_in[2];
    const float* Wv = (const float*)d_in[3];
    const float* Wo = (const float*)d_in[4];
    const float* E  = (const float*)d_in[5];
    const float* F  = (const float*)d_in[6];
    float* out = (float*)d_out;

    __half *hsh, *qh, *oh, *kph, *vph, *hEh, *hFh, *wqh, *wkh, *wvh, *woh;
    cudaGetSymbolAddress((void**)&hsh, g_hs_h);
    cudaGetSymbolAddress((void**)&qh,  g_q_h);
    cudaGetSymbolAddress((void**)&oh,  g_o_h);
    cudaGetSymbolAddress((void**)&kph, g_kp_h);
    cudaGetSymbolAddress((void**)&vph, g_vp_h);
    cudaGetSymbolAddress((void**)&hEh, g_hE_h);
    cudaGetSymbolAddress((void**)&hFh, g_hF_h);
    cudaGetSymbolAddress((void**)&wqh, g_Wq_h);
    cudaGetSymbolAddress((void**)&wkh, g_Wk_h);
    cudaGetSymbolAddress((void**)&wvh, g_Wv_h);
    cudaGetSymbolAddress((void**)&woh, g_Wo_h);

    cudaFuncSetAttribute(gemm_nt_h,  cudaFuncAttributeMaxDynamicSharedMemorySize, SMEM_G);
    cudaFuncSetAttribute(gemm_nt_sk, cudaFuncAttributeMaxDynamicSharedMemorySize, SMEM_G);
    cudaFuncSetAttribute(attn_h,     cudaFuncAttributeMaxDynamicSharedMemorySize, ATTN_SMEM);

    dim3 blk(256);

    conv_hs<<<dim3(QLEN/64, HIDDEN/32, BSZ), dim3(32, 8)>>>(hs);
    conv_w4<<<dim3(HIDDEN*HIDDEN/4/256, 4), blk>>>(Wq, Wk, Wv, Wo);
    transpose_efh<<<dim3(QLEN/64, KP/32, 2), dim3(32, 8)>>>(E, F);

    gemm_nt_sk<<<dim3(16, 2, 16), blk, SMEM_G>>>();
    reduce_hEF<<<2048, blk>>>();

    {
        G aq {hsh, wqh, qh,  nullptr};
        G akp{hEh, wkh, kph, nullptr};
        G avp{hFh, wvh, vph, nullptr};
        gemm_nt_h<<<dim3(16, 128, 3), blk, SMEM_G>>>(aq, akp, avp, HIDDEN, HIDDEN, 8);
    }
    transpose_vp<<<dim3(KP/32, HIDDEN/32, BSZ), dim3(32, 8)>>>();

    attn_h<<<dim3(QLEN/128, HEADS, BSZ), blk, ATTN_SMEM>>>();

    {
        G ao{oh, woh, nullptr, out};
        gemm_nt_h<<<dim3(16, 128, 1), blk, SMEM_G>>>(ao, ao, ao, HIDDEN, HIDDEN, 128);
    }
}

// round 10
// speedup vs baseline: 1.0675x; 1.0675x over previous
#include <cuda_runtime.h>
#include <cuda_fp16.h>
#include <cstdint>

#define HIDDEN 1024
#define HEADS  16
#define HD     64
#define KP     256
#define BSZ    4
#define QLEN   4096
#define MR     (BSZ*QLEN)   // 16384

// ---------------- scratch (device globals) ----------------------------------
__device__ __half g_hs_h [MR*HIDDEN];
__device__ __half g_hs_th[(size_t)BSZ*HIDDEN*QLEN];
__device__ __half g_q_h  [MR*HIDDEN];
__device__ __half g_o_h  [MR*HIDDEN];
__device__ __half g_kp_h [BSZ*KP*HIDDEN];
__device__ __half g_vp_h [BSZ*KP*HIDDEN];
__device__ __half g_vpT_h[BSZ*KP*HIDDEN];
__device__ __half g_hE_h [BSZ*KP*HIDDEN];
__device__ __half g_hF_h [BSZ*KP*HIDDEN];
__device__ __half g_Et_h [KP*QLEN];
__device__ __half g_Ft_h [KP*QLEN];
__device__ __half g_Wq_h [HIDDEN*HIDDEN];
__device__ __half g_Wk_h [HIDDEN*HIDDEN];
__device__ __half g_Wv_h [HIDDEN*HIDDEN];
__device__ float  g_part [16 * KP * HIDDEN];
__device__ __half g_Wo_h [HIDDEN*HIDDEN];

// ============================== helpers =====================================
#define CP_ASYNC16(s, g) \
    asm volatile("cp.async.cg.shared.global [%0], [%1], 16;" :: "r"(s), "l"(g))
#define CP_ASYNC_COMMIT() asm volatile("cp.async.commit_group;")
#define CP_ASYNC_WAIT1()  asm volatile("cp.async.wait_group 1;" ::: "memory")
#define CP_ASYNC_WAIT0()  asm volatile("cp.async.wait_group 0;" ::: "memory")

__device__ __forceinline__ uint32_t smem_u32(const void* p) {
    uint32_t a;
    asm("{ .reg .u64 t; cvta.to.shared.u64 t, %1; cvt.u32.u64 %0, t; }"
        : "=r"(a) : "l"(p));
    return a;
}

#define MMA_F16(c, a0, a1, a2, a3, b0, b1)                                    \
    asm volatile("mma.sync.aligned.m16n8k16.row.col.f32.f16.f16.f32 "         \
        "{%0,%1,%2,%3}, {%4,%5,%6,%7}, {%8,%9}, {%0,%1,%2,%3};"               \
        : "+f"((c)[0]), "+f"((c)[1]), "+f"((c)[2]), "+f"((c)[3])              \
        : "r"(a0), "r"(a1), "r"(a2), "r"(a3), "r"(b0), "r"(b1))

#define LDSM4(d0, d1, d2, d3, a)                                              \
    asm volatile("ldmatrix.sync.aligned.m8n8.x4.shared.b16 {%0,%1,%2,%3}, [%4];" \
        : "=r"(d0), "=r"(d1), "=r"(d2), "=r"(d3) : "r"(a))

// ---- GEMM tiling: BM=BN=128, BK=64 halves, 2-stage (R7 proven) --------------
#define ASTH 72                        // smem row stride (halves); 144B rows
#define ABYT (128*ASTH*2)              // 18432 B per operand tile
#define STG  (2*ABYT)                  // 36864 B per stage
#define SMEM_G (2*STG)                 // 73728 B

struct G { const __half* A; const __half* B; __half* Ch; float* Cf; };

__device__ __forceinline__ void stage_h64(const __half* P, int ldk,
                                          uint32_t sdst, int r0, int k0, int tid)
{
    #pragma unroll
    for (int i = 0; i < 4; i++) {
        int c = tid + i * 256;          // 0..1023
        int row = c >> 3, kc = c & 7;
        CP_ASYNC16(sdst + row * 144 + kc * 16,
                   P + (size_t)(r0 + row) * ldk + k0 + kc * 8);
    }
}

// warp tile 32(m) x 64(n); per BK=64 slab: 24 ldsm4, 64 mma
#define GEMM_SLAB64(bA, bB, aoff, boff, cacc)                                 \
    _Pragma("unroll")                                                         \
    for (int ks2 = 0; ks2 < 4; ks2++) {                                       \
        uint32_t ra0[4], ra1[4];                                              \
        LDSM4(ra0[0], ra0[1], ra0[2], ra0[3], (bA) + (aoff) + ks2*32);        \
        LDSM4(ra1[0], ra1[1], ra1[2], ra1[3],                                 \
              (bA) + (aoff) + 16*ASTH*2 + ks2*32);                            \
        _Pragma("unroll")                                                     \
        for (int jj = 0; jj < 4; jj++) {                                      \
            uint32_t rb[4];                                                   \
            LDSM4(rb[0], rb[1], rb[2], rb[3],                                 \
                  (bB) + (boff) + jj*(16*ASTH*2) + ks2*32);                   \
            MMA_F16(cacc[0][2*jj],   ra0[0],ra0[1],ra0[2],ra0[3], rb[0],rb[2]); \
            MMA_F16(cacc[0][2*jj+1], ra0[0],ra0[1],ra0[2],ra0[3], rb[1],rb[3]); \
            MMA_F16(cacc[1][2*jj],   ra1[0],ra1[1],ra1[2],ra1[3], rb[0],rb[2]); \
            MMA_F16(cacc[1][2*jj+1], ra1[0],ra1[1],ra1[2],ra1[3], rb[1],rb[3]); \
        }                                                                     \
    }

// core mainloop + epilogue shared by both GEMM kernels
__device__ __forceinline__ void gemm_core(
    const __half* A, const __half* B, __half* Ch, float* Cf,
    int N, int ldk, int kbase, int T, int m0, int n0)
{
    extern __shared__ char smem[];
    const int tid = threadIdx.x, lane = tid & 31, wid = tid >> 5;
    const int wm = (wid & 3) * 32, wn = (wid >> 2) * 64;
    const int gq = lane >> 2, r = lane & 3;
    const int lrow = lane & 15, lhi = (lane >> 4) * 8;
    const uint32_t sb = smem_u32(smem);
    const uint32_t aoff = ((wm + lrow) * ASTH + lhi) * 2;
    const uint32_t boff = ((wn + lrow) * ASTH + lhi) * 2;

    float cacc[2][8][4];
    #pragma unroll
    for (int i = 0; i < 2; i++)
        #pragma unroll
        for (int j = 0; j < 8; j++)
            #pragma unroll
            for (int q = 0; q < 4; q++) cacc[i][j][q] = 0.0f;

    stage_h64(A, ldk, sb,        m0, kbase, tid);
    stage_h64(B, ldk, sb + ABYT, n0, kbase, tid);
    CP_ASYNC_COMMIT();

    for (int t = 0; t < T; t++) {
        CP_ASYNC_WAIT0();
        __syncthreads();
        if (t + 1 < T) {
            uint32_t base = sb + ((t + 1) & 1) * STG;
            stage_h64(A, ldk, base,        m0, kbase + (t + 1) * 64, tid);
            stage_h64(B, ldk, base + ABYT, n0, kbase + (t + 1) * 64, tid);
            CP_ASYNC_COMMIT();
        }
        uint32_t bA = sb + (t & 1) * STG;
        uint32_t bB = bA + ABYT;
        GEMM_SLAB64(bA, bB, aoff, boff, cacc);
    }

    #pragma unroll
    for (int i = 0; i < 2; i++) {
        int row = m0 + wm + i * 16 + gq;
        #pragma unroll
        for (int j = 0; j < 8; j++) {
            int col = n0 + wn + j * 8 + r * 2;
            if (Cf) {
                *(float2*)(Cf + (size_t)row * N + col) =
                    make_float2(cacc[i][j][0], cacc[i][j][1]);
                *(float2*)(Cf + (size_t)(row + 8) * N + col) =
                    make_float2(cacc[i][j][2], cacc[i][j][3]);
            } else {
                *(__half2*)(Ch + (size_t)row * N + col) =
                    __floats2half2_rn(cacc[i][j][0], cacc[i][j][1]);
                *(__half2*)(Ch + (size_t)(row + 8) * N + col) =
                    __floats2half2_rn(cacc[i][j][2], cacc[i][j][3]);
            }
        }
    }
}

// ============================================================================
// MEGA GEMM: 1D grid, 1280 blocks.
//   bid <  1024 : q = hs @ Wq^T        (x=bid&7, y=bid>>3, K=1024)
//   bid >= 1024 : split-K hE/hF partial (s=bid-1024: x=s&7, y=(s>>3)&1,
//                 v=s>>4 -> isF=v&1, b=(v>>1)&3, ks=v>>3; K-slab 2048 @4096)
// ============================================================================
__global__ __launch_bounds__(256, 2) void gemm_mega()
{
    const int bid = blockIdx.x;
    if (bid < 1024) {
        gemm_core(g_hs_h, g_Wq_h, g_q_h, nullptr,
                  HIDDEN, HIDDEN, 0, 16,
                  (bid >> 3) * 128, (bid & 7) * 128);
    } else {
        int s = bid - 1024;
        int v = s >> 4;
        int isF = v & 1, b = (v >> 1) & 3, ks = v >> 3;
        const __half* A = isF ? g_Ft_h : g_Et_h;
        const __half* B = g_hs_th + (size_t)b * HIDDEN * QLEN;
        float* Cf = g_part + (size_t)(ks * 8 + (v & 7)) * KP * HIDDEN;
        gemm_core(A, B, nullptr, Cf,
                  HIDDEN, QLEN, ks * 2048, 32,
                  ((s >> 3) & 1) * 128, (s & 7) * 128);
    }
}

// ============================================================================
// Generic NT GEMM (kp/vp and out-proj launches).
// ============================================================================
__global__ __launch_bounds__(256, 2) void gemm_nt_h(G g0, G g1, int N, int K)
{
    const G g = blockIdx.z ? g1 : g0;
    gemm_core(g.A, g.B, g.Ch, g.Cf, N, K, 0, K / 64,
              blockIdx.y * 128, blockIdx.x * 128);
}

__global__ void reduce_hEF()
{
    int idx = blockIdx.x * 256 + threadIdx.x;
    int p = idx >> 16;
    int w4 = idx & 65535;
    const float4 x = ((const float4*)(g_part + (size_t)p       * KP*HIDDEN))[w4];
    const float4 y = ((const float4*)(g_part + (size_t)(8 + p) * KP*HIDDEN))[w4];
    int isF = p & 1, b = p >> 1;
    __half* dst = (isF ? g_hF_h : g_hE_h) + (size_t)b * KP * HIDDEN + w4 * 4;
    ((__half2*)dst)[0] = __floats2half2_rn(x.x + y.x, x.y + y.y);
    ((__half2*)dst)[1] = __floats2half2_rn(x.z + y.z, x.w + y.w);
}

// ============================================================================
// fp16 mma attention: register P, h2exp2 softmax (half the MUFU ops).
// ============================================================================
#define QST 72
#define KST 72
#define VST 264
#define QSO 0
#define KSO (128*QST)
#define VSO (KSO + 256*KST)
#define ATTN_SMEM ((VSO + 64*VST) * 2)  // 89088 B

__global__ __launch_bounds__(256, 2) void attn_h()
{
    extern __shared__ __half smh[];

    const int tid  = threadIdx.x;
    const int lane = tid & 31;
    const int wid  = tid >> 5;
    const int gq   = lane >> 2, r = lane & 3;
    const int lrow = lane & 15, lhi = (lane >> 4) * 8;
    const int q0   = blockIdx.x << 7;
    const int h    = blockIdx.y;
    const int b    = blockIdx.z;

    const __half* qb  = g_q_h  + ((size_t)b*QLEN + q0) * HIDDEN + h*HD;
    const __half* kpb = g_kp_h + (size_t)b*KP*HIDDEN + h*HD;
    const __half* vtb = g_vpT_h + ((size_t)b*HEADS + h) * HD * KP;
    const uint32_t sb = smem_u32(smh);

    // group A: Q + K'
    #pragma unroll
    for (int i = 0; i < 4; i++) {
        int c = tid + i * 256;
        int row = c >> 3, kc = c & 7;
        CP_ASYNC16(sb + (QSO + row * QST) * 2 + kc * 16,
                   qb + (size_t)row * HIDDEN + kc * 8);
    }
    #pragma unroll
    for (int i = 0; i < 8; i++) {
        int c = tid + i * 256;
        int row = c >> 3, kc = c & 7;
        CP_ASYNC16(sb + (KSO + row * KST) * 2 + kc * 16,
                   kpb + (size_t)row * HIDDEN + kc * 8);
    }
    CP_ASYNC_COMMIT();
    // group B: V'^T
    #pragma unroll
    for (int i = 0; i < 8; i++) {
        int c = tid + i * 256;
        int row = c >> 5, kc = c & 31;
        CP_ASYNC16(sb + (VSO + row * VST) * 2 + kc * 16,
                   vtb + (size_t)row * KP + kc * 8);
    }
    CP_ASYNC_COMMIT();

    CP_ASYNC_WAIT1();            // Q+K ready, V still in flight
    __syncthreads();

    const int wm = wid * 16;
    const uint32_t qaoff = sb + ((QSO + (wm + lrow) * QST + lhi) * 2);
    uint32_t QA[4][4];
    #pragma unroll
    for (int ks = 0; ks < 4; ks++)
        LDSM4(QA[ks][0], QA[ks][1], QA[ks][2], QA[ks][3], qaoff + ks * 32);

    // scores -> exp2 in fp16x2 (scale folded: 0.125 * log2(e))
    const float KSC = 0.18033688f;
    const uint32_t kboff = sb + ((KSO + lrow * KST + lhi) * 2);
    uint32_t P[64];
    float sum0 = 0.0f, sum1 = 0.0f;

    #pragma unroll
    for (int jp = 0; jp < 16; jp++) {
        float c0[4] = {0.f, 0.f, 0.f, 0.f};
        float c1[4] = {0.f, 0.f, 0.f, 0.f};
        #pragma unroll
        for (int ks = 0; ks < 4; ks++) {
            uint32_t rb[4];
            LDSM4(rb[0], rb[1], rb[2], rb[3],
                  kboff + jp * (16*KST*2) + ks * 32);
            MMA_F16(c0, QA[ks][0], QA[ks][1], QA[ks][2], QA[ks][3], rb[0], rb[2]);
            MMA_F16(c1, QA[ks][0], QA[ks][1], QA[ks][2], QA[ks][3], rb[1], rb[3]);
        }
        __half2 eA = h2exp2(__floats2half2_rn(c0[0]*KSC, c0[1]*KSC)); // row0 pair
        __half2 eB = h2exp2(__floats2half2_rn(c0[2]*KSC, c0[3]*KSC)); // row1 pair
        __half2 eC = h2exp2(__floats2half2_rn(c1[0]*KSC, c1[1]*KSC));
        __half2 eD = h2exp2(__floats2half2_rn(c1[2]*KSC, c1[3]*KSC));
        P[4*jp + 0] = *(uint32_t*)&eA;
        P[4*jp + 1] = *(uint32_t*)&eB;
        P[4*jp + 2] = *(uint32_t*)&eC;
        P[4*jp + 3] = *(uint32_t*)&eD;
        __half2 t0 = __hadd2(eA, eC);   // row0 contributions (4 values)
        __half2 t1 = __hadd2(eB, eD);   // row1 contributions
        float2 f0 = __half22float2(t0); sum0 += f0.x + f0.y;
        float2 f1 = __half22float2(t1); sum1 += f1.x + f1.y;
    }

    sum0 += __shfl_xor_sync(0xffffffffu, sum0, 1);
    sum0 += __shfl_xor_sync(0xffffffffu, sum0, 2);
    sum1 += __shfl_xor_sync(0xffffffffu, sum1, 1);
    sum1 += __shfl_xor_sync(0xffffffffu, sum1, 2);
    const float ri0 = 1.0f / sum0, ri1 = 1.0f / sum1;

    CP_ASYNC_WAIT0();            // V ready
    __syncthreads();

    const uint32_t vboff = sb + ((VSO + lrow * VST + lhi) * 2);
    float c2[8][4];
    #pragma unroll
    for (int j = 0; j < 8; j++)
        #pragma unroll
        for (int q = 0; q < 4; q++) c2[j][q] = 0.0f;

    #pragma unroll
    for (int t = 0; t < 16; t++) {
        #pragma unroll
        for (int g = 0; g < 4; g++) {
            uint32_t rb[4];
            LDSM4(rb[0], rb[1], rb[2], rb[3],
                  vboff + g * (16*VST*2) + t * 32);
            MMA_F16(c2[2*g],   P[4*t+0], P[4*t+1], P[4*t+2], P[4*t+3], rb[0], rb[2]);
            MMA_F16(c2[2*g+1], P[4*t+0], P[4*t+1], P[4*t+2], P[4*t+3], rb[1], rb[3]);
        }
    }

    __half* ob = g_o_h + ((size_t)b*QLEN + q0 + wm) * HIDDEN + h*HD;
    #pragma unroll
    for (int j = 0; j < 8; j++) {
        int col = j * 8 + r * 2;
        *(__half2*)(ob + (size_t)gq * HIDDEN + col) =
            __floats2half2_rn(c2[j][0] * ri0, c2[j][1] * ri0);
        *(__half2*)(ob + (size_t)(gq + 8) * HIDDEN + col) =
            __floats2half2_rn(c2[j][2] * ri1, c2[j][3] * ri1);
    }
}

// ============================================================================
// Conversion / transpose pre-passes (unchanged)
// ============================================================================
__global__ void conv_hs(const float* __restrict__ hs)
{
    __shared__ float t[64][33];
    int b = blockIdx.z;
    int s0 = blockIdx.x * 64, n0 = blockIdx.y * 32;
    int tx = threadIdx.x, ty = threadIdx.y;
    #pragma unroll
    for (int i = 0; i < 8; i++) {
        int s = s0 + ty + i * 8;
        float v = hs[((size_t)b * QLEN + s) * HIDDEN + n0 + tx];
        t[ty + i * 8][tx] = v;
        g_hs_h[((size_t)b * QLEN + s) * HIDDEN + n0 + tx] = __float2half_rn(v);
    }
    __syncthreads();
    #pragma unroll
    for (int i = 0; i < 4; i++) {
        int n = n0 + ty + i * 8;
        __half2 hv = __floats2half2_rn(t[2*tx][ty + i * 8], t[2*tx + 1][ty + i * 8]);
        *(__half2*)&g_hs_th[((size_t)b * HIDDEN + n) * QLEN + s0 + 2*tx] = hv;
    }
}

__global__ void conv_w4(const float* w0, const float* w1,
                        const float* w2, const float* w3)
{
    const float* src = (blockIdx.y == 0) ? w0 : (blockIdx.y == 1) ? w1
                     : (blockIdx.y == 2) ? w2 : w3;
    __half* dst = (blockIdx.y == 0) ? g_Wq_h : (blockIdx.y == 1) ? g_Wk_h
                : (blockIdx.y == 2) ? g_Wv_h : g_Wo_h;
    int i = blockIdx.x * 256 + threadIdx.x;
    float4 v = ((const float4*)src)[i];
    ((__half2*)dst)[i*2]   = __floats2half2_rn(v.x, v.y);
    ((__half2*)dst)[i*2+1] = __floats2half2_rn(v.z, v.w);
}

__global__ void transpose_efh(const float* __restrict__ E, const float* __restrict__ F)
{
    __shared__ float t[64][33];
    const float* src = blockIdx.z ? F : E;
    __half* dst = blockIdx.z ? g_Ft_h : g_Et_h;
    int s0 = blockIdx.x * 64, m0 = blockIdx.y * 32;
    int tx = threadIdx.x, ty = threadIdx.y;
    #pragma unroll
    for (int i = 0; i < 8; i++)
        t[ty + i * 8][tx] = src[(size_t)(s0 + ty + i * 8) * KP + m0 + tx];
    __syncthreads();
    #pragma unroll
    for (int i = 0; i < 4; i++) {
        int m = m0 + ty + i * 8;
        __half2 hv = __floats2half2_rn(t[2*tx][ty + i * 8], t[2*tx + 1][ty + i * 8]);
        *(__half2*)&dst[(size_t)m * QLEN + s0 + 2*tx] = hv;
    }
}

__global__ void transpose_vp()
{
    __shared__ __half t[32][33];
    int b = blockIdx.z;
    int k0 = blockIdx.x * 32, n0 = blockIdx.y * 32;
    int tx = threadIdx.x, ty = threadIdx.y;
    #pragma unroll
    for (int i = 0; i < 4; i++)
        t[ty + i * 8][tx] =
            g_vp_h[((size_t)b * KP + k0 + ty + i * 8) * HIDDEN + n0 + tx];
    __syncthreads();
    #pragma unroll
    for (int i = 0; i < 4; i++)
        g_vpT_h[((size_t)b * HIDDEN + n0 + ty + i * 8) * KP + k0 + tx] =
            t[tx][ty + i * 8];
}

// ---------------------------------------------------------------------------
extern "C" void kernel_launch(void* const* d_in, const int* in_sizes, int n_in,
                              void* d_out, int out_size)
{
    const float* hs = (const float*)d_in[0];
    const float* Wq = (const float*)d_in[1];
    const float* Wk = (const float*)d_in[2];
    const float* Wv = (const float*)d_in[3];
    const float* Wo = (const float*)d_in[4];
    const float* E  = (const float*)d_in[5];
    const float* F  = (const float*)d_in[6];
    float* out = (float*)d_out;

    __half *oh, *kph, *vph, *hEh, *hFh, *wkh, *wvh, *woh;
    cudaGetSymbolAddress((void**)&oh,  g_o_h);
    cudaGetSymbolAddress((void**)&kph, g_kp_h);
    cudaGetSymbolAddress((void**)&vph, g_vp_h);
    cudaGetSymbolAddress((void**)&hEh, g_hE_h);
    cudaGetSymbolAddress((void**)&hFh, g_hF_h);
    cudaGetSymbolAddress((void**)&wkh, g_Wk_h);
    cudaGetSymbolAddress((void**)&wvh, g_Wv_h);
    cudaGetSymbolAddress((void**)&woh, g_Wo_h);

    cudaFuncSetAttribute(gemm_mega, cudaFuncAttributeMaxDynamicSharedMemorySize, SMEM_G);
    cudaFuncSetAttribute(gemm_nt_h, cudaFuncAttributeMaxDynamicSharedMemorySize, SMEM_G);
    cudaFuncSetAttribute(attn_h,    cudaFuncAttributeMaxDynamicSharedMemorySize, ATTN_SMEM);

    dim3 blk(256);

    // pre-passes
    conv_hs<<<dim3(QLEN/64, HIDDEN/32, BSZ), dim3(32, 8)>>>(hs);
    conv_w4<<<dim3(HIDDEN*HIDDEN/4/256, 4), blk>>>(Wq, Wk, Wv, Wo);
    transpose_efh<<<dim3(QLEN/64, KP/32, 2), dim3(32, 8)>>>(E, F);

    // fused: q-projection (1024 blocks) + split-K hE/hF partials (256 blocks)
    gemm_mega<<<1280, blk, SMEM_G>>>();
    reduce_hEF<<<2048, blk>>>();

    // kp = hE @ Wk^T | vp = hF @ Wv^T
    {
        G a0{hEh, wkh, kph, nullptr}, a1{hFh, wvh, vph, nullptr};
        gemm_nt_h<<<dim3(8, 8, 2), blk, SMEM_G>>>(a0, a1, HIDDEN, HIDDEN);
    }
    transpose_vp<<<dim3(KP/32, HIDDEN/32, BSZ), dim3(32, 8)>>>();

    // attention
    attn_h<<<dim3(QLEN/128, HEADS, BSZ), blk, ATTN_SMEM>>>();

    // out = o @ Wo^T (fp32 to d_out)
    {
        G ao{oh, woh, nullptr, out};
        gemm_nt_h<<<dim3(8, 128, 1), blk, SMEM_G>>>(ao, ao, HIDDEN, HIDDEN);
    }
}

// round 11
// speedup vs baseline: 1.0834x; 1.0149x over previous
#include <cuda_runtime.h>
#include <cuda_fp16.h>
#include <cstdint>

#define HIDDEN 1024
#define HEADS  16
#define HD     64
#define KP     256
#define BSZ    4
#define QLEN   4096
#define MR     (BSZ*QLEN)   // 16384

// ---------------- scratch (device globals) ----------------------------------
__device__ __half g_hs_h [MR*HIDDEN];
__device__ __half g_hs_th[(size_t)BSZ*HIDDEN*QLEN];
__device__ __half g_q_h  [MR*HIDDEN];
__device__ __half g_o_h  [MR*HIDDEN];
__device__ __half g_kp_h [BSZ*KP*HIDDEN];
__device__ __half g_vp_h [BSZ*KP*HIDDEN];
__device__ __half g_hE_h [BSZ*KP*HIDDEN];
__device__ __half g_hF_h [BSZ*KP*HIDDEN];
__device__ __half g_Et_h [KP*QLEN];
__device__ __half g_Ft_h [KP*QLEN];
__device__ __half g_Wq_h [HIDDEN*HIDDEN];
__device__ __half g_Wk_h [HIDDEN*HIDDEN];
__device__ __half g_Wv_h [HIDDEN*HIDDEN];
__device__ float  g_part [16 * KP * HIDDEN];
__device__ __half g_Wo_h [HIDDEN*HIDDEN];

// ============================== helpers =====================================
#define CP_ASYNC16(s, g) \
    asm volatile("cp.async.cg.shared.global [%0], [%1], 16;" :: "r"(s), "l"(g))
#define CP_ASYNC_COMMIT() asm volatile("cp.async.commit_group;")
#define CP_ASYNC_WAIT1()  asm volatile("cp.async.wait_group 1;" ::: "memory")
#define CP_ASYNC_WAIT0()  asm volatile("cp.async.wait_group 0;" ::: "memory")

__device__ __forceinline__ uint32_t smem_u32(const void* p) {
    uint32_t a;
    asm("{ .reg .u64 t; cvta.to.shared.u64 t, %1; cvt.u32.u64 %0, t; }"
        : "=r"(a) : "l"(p));
    return a;
}

#define MMA_F16(c, a0, a1, a2, a3, b0, b1)                                    \
    asm volatile("mma.sync.aligned.m16n8k16.row.col.f32.f16.f16.f32 "         \
        "{%0,%1,%2,%3}, {%4,%5,%6,%7}, {%8,%9}, {%0,%1,%2,%3};"               \
        : "+f"((c)[0]), "+f"((c)[1]), "+f"((c)[2]), "+f"((c)[3])              \
        : "r"(a0), "r"(a1), "r"(a2), "r"(a3), "r"(b0), "r"(b1))

#define LDSM4(d0, d1, d2, d3, a)                                              \
    asm volatile("ldmatrix.sync.aligned.m8n8.x4.shared.b16 {%0,%1,%2,%3}, [%4];" \
        : "=r"(d0), "=r"(d1), "=r"(d2), "=r"(d3) : "r"(a))

#define LDSM4T(d0, d1, d2, d3, a)                                             \
    asm volatile("ldmatrix.sync.aligned.m8n8.x4.trans.shared.b16 {%0,%1,%2,%3}, [%4];" \
        : "=r"(d0), "=r"(d1), "=r"(d2), "=r"(d3) : "r"(a))

// ---- GEMM tiling: BM=BN=128, BK=64 halves, 2-stage ---------------------------
#define ASTH 72                        // smem row stride (halves); 144B rows
#define ABYT (128*ASTH*2)              // 18432 B per operand tile
#define STG  (2*ABYT)                  // 36864 B per stage
#define SMEM_G (2*STG)                 // 73728 B

struct G { const __half* A; const __half* B; __half* Ch; float* Cf; };

__device__ __forceinline__ void stage_h64(const __half* P, int ldk,
                                          uint32_t sdst, int r0, int k0, int tid)
{
    #pragma unroll
    for (int i = 0; i < 4; i++) {
        int c = tid + i * 256;          // 0..1023
        int row = c >> 3, kc = c & 7;
        CP_ASYNC16(sdst + row * 144 + kc * 16,
                   P + (size_t)(r0 + row) * ldk + k0 + kc * 8);
    }
}

// core mainloop (explicit fragment double-buffering) + epilogue
__device__ __forceinline__ void gemm_core(
    const __half* A, const __half* B, __half* Ch, float* Cf,
    int N, int ldk, int kbase, int T, int m0, int n0)
{
    extern __shared__ char smem[];
    const int tid = threadIdx.x, lane = tid & 31, wid = tid >> 5;
    const int wm = (wid & 3) * 32, wn = (wid >> 2) * 64;
    const int gq = lane >> 2, r = lane & 3;
    const int lrow = lane & 15, lhi = (lane >> 4) * 8;
    const uint32_t sb = smem_u32(smem);
    const uint32_t aoff = ((wm + lrow) * ASTH + lhi) * 2;
    const uint32_t boff = ((wn + lrow) * ASTH + lhi) * 2;

    float cacc[2][8][4];
    #pragma unroll
    for (int i = 0; i < 2; i++)
        #pragma unroll
        for (int j = 0; j < 8; j++)
            #pragma unroll
            for (int q = 0; q < 4; q++) cacc[i][j][q] = 0.0f;

    stage_h64(A, ldk, sb,        m0, kbase, tid);
    stage_h64(B, ldk, sb + ABYT, n0, kbase, tid);
    CP_ASYNC_COMMIT();

    for (int t = 0; t < T; t++) {
        CP_ASYNC_WAIT0();
        __syncthreads();
        if (t + 1 < T) {
            uint32_t base = sb + ((t + 1) & 1) * STG;
            stage_h64(A, ldk, base,        m0, kbase + (t + 1) * 64, tid);
            stage_h64(B, ldk, base + ABYT, n0, kbase + (t + 1) * 64, tid);
            CP_ASYNC_COMMIT();
        }
        const uint32_t bA = sb + (t & 1) * STG;
        const uint32_t bB = bA + ABYT;

        uint32_t fa[2][8], fb[2][16];
        // ks = 0 fragments
        LDSM4(fa[0][0], fa[0][1], fa[0][2], fa[0][3], bA + aoff);
        LDSM4(fa[0][4], fa[0][5], fa[0][6], fa[0][7], bA + aoff + 16*ASTH*2);
        #pragma unroll
        for (int jj = 0; jj < 4; jj++)
            LDSM4(fb[0][4*jj], fb[0][4*jj+1], fb[0][4*jj+2], fb[0][4*jj+3],
                  bB + boff + jj*(16*ASTH*2));

        #pragma unroll
        for (int ks = 0; ks < 4; ks++) {
            const int cur = ks & 1, nxt = cur ^ 1;
            if (ks < 3) {   // prefetch ks+1 fragments before compute of ks
                LDSM4(fa[nxt][0], fa[nxt][1], fa[nxt][2], fa[nxt][3],
                      bA + aoff + (ks+1)*32);
                LDSM4(fa[nxt][4], fa[nxt][5], fa[nxt][6], fa[nxt][7],
                      bA + aoff + 16*ASTH*2 + (ks+1)*32);
                #pragma unroll
                for (int jj = 0; jj < 4; jj++)
                    LDSM4(fb[nxt][4*jj], fb[nxt][4*jj+1],
                          fb[nxt][4*jj+2], fb[nxt][4*jj+3],
                          bB + boff + jj*(16*ASTH*2) + (ks+1)*32);
            }
            #pragma unroll
            for (int jj = 0; jj < 4; jj++) {
                MMA_F16(cacc[0][2*jj],   fa[cur][0], fa[cur][1], fa[cur][2], fa[cur][3],
                        fb[cur][4*jj],   fb[cur][4*jj+2]);
                MMA_F16(cacc[0][2*jj+1], fa[cur][0], fa[cur][1], fa[cur][2], fa[cur][3],
                        fb[cur][4*jj+1], fb[cur][4*jj+3]);
                MMA_F16(cacc[1][2*jj],   fa[cur][4], fa[cur][5], fa[cur][6], fa[cur][7],
                        fb[cur][4*jj],   fb[cur][4*jj+2]);
                MMA_F16(cacc[1][2*jj+1], fa[cur][4], fa[cur][5], fa[cur][6], fa[cur][7],
                        fb[cur][4*jj+1], fb[cur][4*jj+3]);
            }
        }
    }

    #pragma unroll
    for (int i = 0; i < 2; i++) {
        int row = m0 + wm + i * 16 + gq;
        #pragma unroll
        for (int j = 0; j < 8; j++) {
            int col = n0 + wn + j * 8 + r * 2;
            if (Cf) {
                *(float2*)(Cf + (size_t)row * N + col) =
                    make_float2(cacc[i][j][0], cacc[i][j][1]);
                *(float2*)(Cf + (size_t)(row + 8) * N + col) =
                    make_float2(cacc[i][j][2], cacc[i][j][3]);
            } else {
                *(__half2*)(Ch + (size_t)row * N + col) =
                    __floats2half2_rn(cacc[i][j][0], cacc[i][j][1]);
                *(__half2*)(Ch + (size_t)(row + 8) * N + col) =
                    __floats2half2_rn(cacc[i][j][2], cacc[i][j][3]);
            }
        }
    }
}

// ============================================================================
// MEGA GEMM: bid<1024 -> q-projection; else split-K hE/hF partials.
// ============================================================================
__global__ __launch_bounds__(256, 2) void gemm_mega()
{
    const int bid = blockIdx.x;
    if (bid < 1024) {
        gemm_core(g_hs_h, g_Wq_h, g_q_h, nullptr,
                  HIDDEN, HIDDEN, 0, 16,
                  (bid >> 3) * 128, (bid & 7) * 128);
    } else {
        int s = bid - 1024;
        int v = s >> 4;
        int isF = v & 1, b = (v >> 1) & 3, ks = v >> 3;
        const __half* A = isF ? g_Ft_h : g_Et_h;
        const __half* B = g_hs_th + (size_t)b * HIDDEN * QLEN;
        float* Cf = g_part + (size_t)(ks * 8 + (v & 7)) * KP * HIDDEN;
        gemm_core(A, B, nullptr, Cf,
                  HIDDEN, QLEN, ks * 2048, 32,
                  ((s >> 3) & 1) * 128, (s & 7) * 128);
    }
}

__global__ __launch_bounds__(256, 2) void gemm_nt_h(G g0, G g1, int N, int K)
{
    const G g = blockIdx.z ? g1 : g0;
    gemm_core(g.A, g.B, g.Ch, g.Cf, N, K, 0, K / 64,
              blockIdx.y * 128, blockIdx.x * 128);
}

__global__ void reduce_hEF()
{
    int idx = blockIdx.x * 256 + threadIdx.x;
    int p = idx >> 16;
    int w4 = idx & 65535;
    const float4 x = ((const float4*)(g_part + (size_t)p       * KP*HIDDEN))[w4];
    const float4 y = ((const float4*)(g_part + (size_t)(8 + p) * KP*HIDDEN))[w4];
    int isF = p & 1, b = p >> 1;
    __half* dst = (isF ? g_hF_h : g_hE_h) + (size_t)b * KP * HIDDEN + w4 * 4;
    ((__half2*)dst)[0] = __floats2half2_rn(x.x + y.x, x.y + y.y);
    ((__half2*)dst)[1] = __floats2half2_rn(x.z + y.z, x.w + y.w);
}

// ============================================================================
// fp16 mma attention: register P, h2exp2 softmax, ldmatrix.trans for V
// (V staged directly from kp/vp-layout gmem — no transpose kernel).
// ============================================================================
#define QST 72
#define KST 72
#define VST 72
#define QSO 0
#define KSO (128*QST)                   // 9216
#define VSO (KSO + 256*KST)             // 27648
#define ATTN_SMEM ((VSO + 256*VST) * 2) // 92160 B

__global__ __launch_bounds__(256, 2) void attn_h()
{
    extern __shared__ __half smh[];

    const int tid  = threadIdx.x;
    const int lane = tid & 31;
    const int wid  = tid >> 5;
    const int gq   = lane >> 2, r = lane & 3;
    const int lrow = lane & 15, lhi = (lane >> 4) * 8;
    const int q0   = blockIdx.x << 7;
    const int h    = blockIdx.y;
    const int b    = blockIdx.z;

    const __half* qb  = g_q_h  + ((size_t)b*QLEN + q0) * HIDDEN + h*HD;
    const __half* kpb = g_kp_h + (size_t)b*KP*HIDDEN + h*HD;
    const __half* vpb = g_vp_h + (size_t)b*KP*HIDDEN + h*HD;  // [256 keys][64 d]
    const uint32_t sb = smem_u32(smh);

    // group A: Q + K'
    #pragma unroll
    for (int i = 0; i < 4; i++) {
        int c = tid + i * 256;
        int row = c >> 3, kc = c & 7;
        CP_ASYNC16(sb + (QSO + row * QST) * 2 + kc * 16,
                   qb + (size_t)row * HIDDEN + kc * 8);
    }
    #pragma unroll
    for (int i = 0; i < 8; i++) {
        int c = tid + i * 256;
        int row = c >> 3, kc = c & 7;
        CP_ASYNC16(sb + (KSO + row * KST) * 2 + kc * 16,
                   kpb + (size_t)row * HIDDEN + kc * 8);
    }
    CP_ASYNC_COMMIT();
    // group B: V' rows (key-major, d contiguous)
    #pragma unroll
    for (int i = 0; i < 8; i++) {
        int c = tid + i * 256;
        int row = c >> 3, kc = c & 7;
        CP_ASYNC16(sb + (VSO + row * VST) * 2 + kc * 16,
                   vpb + (size_t)row * HIDDEN + kc * 8);
    }
    CP_ASYNC_COMMIT();

    CP_ASYNC_WAIT1();            // Q+K ready, V still in flight
    __syncthreads();

    const int wm = wid * 16;
    const uint32_t qaoff = sb + ((QSO + (wm + lrow) * QST + lhi) * 2);
    uint32_t QA[4][4];
    #pragma unroll
    for (int ks = 0; ks < 4; ks++)
        LDSM4(QA[ks][0], QA[ks][1], QA[ks][2], QA[ks][3], qaoff + ks * 32);

    // scores -> exp2 in fp16x2 (scale folded: 0.125 * log2(e))
    const float KSC = 0.18033688f;
    const uint32_t kboff = sb + ((KSO + lrow * KST + lhi) * 2);
    uint32_t P[64];
    float sum0 = 0.0f, sum1 = 0.0f;

    #pragma unroll
    for (int jp = 0; jp < 16; jp++) {
        float c0[4] = {0.f, 0.f, 0.f, 0.f};
        float c1[4] = {0.f, 0.f, 0.f, 0.f};
        #pragma unroll
        for (int ks = 0; ks < 4; ks++) {
            uint32_t rb[4];
            LDSM4(rb[0], rb[1], rb[2], rb[3],
                  kboff + jp * (16*KST*2) + ks * 32);
            MMA_F16(c0, QA[ks][0], QA[ks][1], QA[ks][2], QA[ks][3], rb[0], rb[2]);
            MMA_F16(c1, QA[ks][0], QA[ks][1], QA[ks][2], QA[ks][3], rb[1], rb[3]);
        }
        __half2 eA = h2exp2(__floats2half2_rn(c0[0]*KSC, c0[1]*KSC));
        __half2 eB = h2exp2(__floats2half2_rn(c0[2]*KSC, c0[3]*KSC));
        __half2 eC = h2exp2(__floats2half2_rn(c1[0]*KSC, c1[1]*KSC));
        __half2 eD = h2exp2(__floats2half2_rn(c1[2]*KSC, c1[3]*KSC));
        P[4*jp + 0] = *(uint32_t*)&eA;
        P[4*jp + 1] = *(uint32_t*)&eB;
        P[4*jp + 2] = *(uint32_t*)&eC;
        P[4*jp + 3] = *(uint32_t*)&eD;
        __half2 t0 = __hadd2(eA, eC);
        __half2 t1 = __hadd2(eB, eD);
        float2 f0 = __half22float2(t0); sum0 += f0.x + f0.y;
        float2 f1 = __half22float2(t1); sum1 += f1.x + f1.y;
    }

    sum0 += __shfl_xor_sync(0xffffffffu, sum0, 1);
    sum0 += __shfl_xor_sync(0xffffffffu, sum0, 2);
    sum1 += __shfl_xor_sync(0xffffffffu, sum1, 1);
    sum1 += __shfl_xor_sync(0xffffffffu, sum1, 2);
    const float ri0 = 1.0f / sum0, ri1 = 1.0f / sum1;

    CP_ASYNC_WAIT0();            // V ready
    __syncthreads();

    // PV: A from P registers; B via ldmatrix.trans on V[key][d] tiles.
    float c2[8][4];
    #pragma unroll
    for (int j = 0; j < 8; j++)
        #pragma unroll
        for (int q = 0; q < 4; q++) c2[j][q] = 0.0f;

    #pragma unroll
    for (int t = 0; t < 16; t++) {
        #pragma unroll
        for (int g = 0; g < 4; g++) {
            uint32_t rb[4];
            // rows = keys (t*16 + lrow), cols = d (g*16 + lhi)
            LDSM4T(rb[0], rb[1], rb[2], rb[3],
                   sb + ((VSO + (t*16 + lrow) * VST + g*16 + lhi) * 2));
            // trans pairing: (rb0,rb1) = d-tile g.lo, (rb2,rb3) = d-tile g.hi
            MMA_F16(c2[2*g],   P[4*t+0], P[4*t+1], P[4*t+2], P[4*t+3], rb[0], rb[1]);
            MMA_F16(c2[2*g+1], P[4*t+0], P[4*t+1], P[4*t+2], P[4*t+3], rb[2], rb[3]);
        }
    }

    __half* ob = g_o_h + ((size_t)b*QLEN + q0 + wm) * HIDDEN + h*HD;
    #pragma unroll
    for (int j = 0; j < 8; j++) {
        int col = j * 8 + r * 2;
        *(__half2*)(ob + (size_t)gq * HIDDEN + col) =
            __floats2half2_rn(c2[j][0] * ri0, c2[j][1] * ri0);
        *(__half2*)(ob + (size_t)(gq + 8) * HIDDEN + col) =
            __floats2half2_rn(c2[j][2] * ri1, c2[j][3] * ri1);
    }
}

// ============================================================================
// Unified pre-pass: conv_hs (8192 blk) | conv_w4 (4096 blk) | efh (1024 blk)
// block (32, 8)
// ============================================================================
__global__ void prep(const float* __restrict__ hs,
                     const float* __restrict__ w0, const float* __restrict__ w1,
                     const float* __restrict__ w2, const float* __restrict__ w3,
                     const float* __restrict__ E,  const float* __restrict__ F)
{
    __shared__ float t[64][33];
    const int bid = blockIdx.x;
    const int tx = threadIdx.x, ty = threadIdx.y;

    if (bid < 8192) {               // ---- conv_hs: hs -> hs_h + hs_th -------
        int x = bid & 63, y = (bid >> 6) & 31, b = bid >> 11;
        int s0 = x * 64, n0 = y * 32;
        #pragma unroll
        for (int i = 0; i < 8; i++) {
            int s = s0 + ty + i * 8;
            float v = hs[((size_t)b * QLEN + s) * HIDDEN + n0 + tx];
            t[ty + i * 8][tx] = v;
            g_hs_h[((size_t)b * QLEN + s) * HIDDEN + n0 + tx] = __float2half_rn(v);
        }
        __syncthreads();
        #pragma unroll
        for (int i = 0; i < 4; i++) {
            int n = n0 + ty + i * 8;
            __half2 hv = __floats2half2_rn(t[2*tx][ty + i * 8], t[2*tx + 1][ty + i * 8]);
            *(__half2*)&g_hs_th[((size_t)b * HIDDEN + n) * QLEN + s0 + 2*tx] = hv;
        }
    } else if (bid < 12288) {       // ---- conv_w4 ---------------------------
        int s = bid - 8192;
        int mat = s >> 10;
        const float* src = (mat == 0) ? w0 : (mat == 1) ? w1 : (mat == 2) ? w2 : w3;
        __half* dst = (mat == 0) ? g_Wq_h : (mat == 1) ? g_Wk_h
                    : (mat == 2) ? g_Wv_h : g_Wo_h;
        int i = (s & 1023) * 256 + ty * 32 + tx;
        float4 v = ((const float4*)src)[i];
        ((__half2*)dst)[i*2]   = __floats2half2_rn(v.x, v.y);
        ((__half2*)dst)[i*2+1] = __floats2half2_rn(v.z, v.w);
    } else {                        // ---- transpose_efh ---------------------
        int s = bid - 12288;
        int z = s >> 9, rem = s & 511;
        int x = rem & 63, y = rem >> 6;
        const float* src = z ? F : E;
        __half* dst = z ? g_Ft_h : g_Et_h;
        int s0 = x * 64, m0 = y * 32;
        #pragma unroll
        for (int i = 0; i < 8; i++)
            t[ty + i * 8][tx] = src[(size_t)(s0 + ty + i * 8) * KP + m0 + tx];
        __syncthreads();
        #pragma unroll
        for (int i = 0; i < 4; i++) {
            int m = m0 + ty + i * 8;
            __half2 hv = __floats2half2_rn(t[2*tx][ty + i * 8], t[2*tx + 1][ty + i * 8]);
            *(__half2*)&dst[(size_t)m * QLEN + s0 + 2*tx] = hv;
        }
    }
}

// ---------------------------------------------------------------------------
extern "C" void kernel_launch(void* const* d_in, const int* in_sizes, int n_in,
                              void* d_out, int out_size)
{
    const float* hs = (const float*)d_in[0];
    const float* Wq = (const float*)d_in[1];
    const float* Wk = (const float*)d_in[2];
    const float* Wv = (const float*)d_in[3];
    const float* Wo = (const float*)d_in[4];
    const float* E  = (const float*)d_in[5];
    const float* F  = (const float*)d_in[6];
    float* out = (float*)d_out;

    __half *oh, *kph, *vph, *hEh, *hFh, *wkh, *wvh, *woh;
    cudaGetSymbolAddress((void**)&oh,  g_o_h);
    cudaGetSymbolAddress((void**)&kph, g_kp_h);
    cudaGetSymbolAddress((void**)&vph, g_vp_h);
    cudaGetSymbolAddress((void**)&hEh, g_hE_h);
    cudaGetSymbolAddress((void**)&hFh, g_hF_h);
    cudaGetSymbolAddress((void**)&wkh, g_Wk_h);
    cudaGetSymbolAddress((void**)&wvh, g_Wv_h);
    cudaGetSymbolAddress((void**)&woh, g_Wo_h);

    cudaFuncSetAttribute(gemm_mega, cudaFuncAttributeMaxDynamicSharedMemorySize, SMEM_G);
    cudaFuncSetAttribute(gemm_nt_h, cudaFuncAttributeMaxDynamicSharedMemorySize, SMEM_G);
    cudaFuncSetAttribute(attn_h,    cudaFuncAttributeMaxDynamicSharedMemorySize, ATTN_SMEM);

    dim3 blk(256);

    // unified pre-pass
    prep<<<13312, dim3(32, 8)>>>(hs, Wq, Wk, Wv, Wo, E, F);

    // fused: q-projection + split-K hE/hF partials
    gemm_mega<<<1280, blk, SMEM_G>>>();
    reduce_hEF<<<2048, blk>>>();

    // kp = hE @ Wk^T | vp = hF @ Wv^T
    {
        G a0{hEh, wkh, kph, nullptr}, a1{hFh, wvh, vph, nullptr};
        gemm_nt_h<<<dim3(8, 8, 2), blk, SMEM_G>>>(a0, a1, HIDDEN, HIDDEN);
    }

    // attention (V transposed in-register via ldmatrix.trans)
    attn_h<<<dim3(QLEN/128, HEADS, BSZ), blk, ATTN_SMEM>>>();

    // out = o @ Wo^T (fp32 to d_out)
    {
        G ao{oh, woh, nullptr, out};
        gemm_nt_h<<<dim3(8, 128, 1), blk, SMEM_G>>>(ao, ao, HIDDEN, HIDDEN);
    }
}